// round 4
// baseline (speedup 1.0000x reference)
#include <cuda_runtime.h>
#include <cuda_bf16.h>

// PatternAwareLoss: mean over (B,S,L) of boost*mask*(softplus(x) - x*y) / sum(mask)
// B=64, S=8192, L=24. boost[b,s]=1.2 if any-label(s) && any-label(s+1) && s<S-1 else 1.
//
// Strategy: one thread per (b,s) position (24 elems). softplus(x) = relu(x) +
// ln2*log2(1+exp2(-log2e*|x|)) -> 2 MUFU (EX2,LG2) + ~8 fixed-pipe ops per elem.
// has_punct propagated across positions with __shfl_down (warp = 32 consecutive
// positions, S%32==0 so no batch crossing inside a warp); lane31 halo-loads the
// next position's labels. Deterministic hierarchical reduction (no atomics).

#define NPOS   (64 * 8192)     // B*S
#define S_LEN  8192
#define L_DIM  24
#define TPB    256
#define NBLK   (NPOS / TPB)    // 2048

__device__ float2 g_part[NBLK];

__device__ __forceinline__ void proc_elem(float x, int y, float& sm, float& sl) {
    // sl += log2(1 + exp(-|x|));  sm += max(x,0) - x*y
    float a = fabsf(x);
    float e = __expf(-a);              // FMUL + MUFU.EX2
    sl += __log2f(1.0f + e);           // FADD + MUFU.LG2 + FADD (ln2 scale hoisted)
    sm += fmaxf(x, 0.0f) - x * (float)y;
}

__global__ __launch_bounds__(TPB) void loss_main_kernel(
    const float* __restrict__ logits,
    const int*   __restrict__ labels,
    const float* __restrict__ attn_mask)
{
    const int p = blockIdx.x * TPB + threadIdx.x;   // position index in [0, NPOS)
    const unsigned lane = threadIdx.x & 31u;

    const float4* __restrict__ lg4 = reinterpret_cast<const float4*>(logits + (size_t)p * L_DIM);
    const int4*   __restrict__ lb4 = reinterpret_cast<const int4*>(labels + (size_t)p * L_DIM);

    // 4 parallel accumulator pairs for ILP across the dependent-add chains.
    float sm0 = 0.f, sm1 = 0.f, sm2 = 0.f, sm3 = 0.f;
    float sl0 = 0.f, sl1 = 0.f, sl2 = 0.f, sl3 = 0.f;
    int   orr = 0;

#pragma unroll
    for (int i = 0; i < L_DIM / 4; i++) {   // 6 iterations
        float4 x = lg4[i];
        int4   y = lb4[i];
        orr |= (y.x | y.y | y.z | y.w);
        proc_elem(x.x, y.x, sm0, sl0);
        proc_elem(x.y, y.y, sm1, sl1);
        proc_elem(x.z, y.z, sm2, sl2);
        proc_elem(x.w, y.w, sm3, sl3);
    }

    float sm = (sm0 + sm1) + (sm2 + sm3);
    float sl = (sl0 + sl1) + (sl2 + sl3);
    float possum = fmaf(0.69314718055994531f, sl, sm);   // ln2 * sum(log2) + sum(relu - xy)

    int hp = (orr != 0) ? 1 : 0;

    // hp of position p+1: from neighbor lane; lane 31 halo-loads next position.
    int hp_next = __shfl_down_sync(0xffffffffu, hp, 1);
    if (lane == 31u) {
        hp_next = 0;
        if (((p + 1) & (S_LEN - 1)) != 0) {   // p+1 in same batch (also guards global end)
            const int4* nb4 = reinterpret_cast<const int4*>(labels + (size_t)(p + 1) * L_DIM);
            int o2 = 0;
#pragma unroll
            for (int i = 0; i < L_DIM / 4; i++) {
                int4 t = nb4[i];
                o2 |= (t.x | t.y | t.z | t.w);
            }
            hp_next = (o2 != 0) ? 1 : 0;
        }
    }

    const int s_in_batch = p & (S_LEN - 1);
    const float boost = (s_in_batch != (S_LEN - 1) && hp && hp_next) ? 1.2f : 1.0f;
    const float m = attn_mask[p];

    float num = m * boost * possum;
    float den = m;

    // warp reduce (pairwise, deterministic)
#pragma unroll
    for (int off = 16; off > 0; off >>= 1) {
        num += __shfl_down_sync(0xffffffffu, num, off);
        den += __shfl_down_sync(0xffffffffu, den, off);
    }

    __shared__ float2 wsum[TPB / 32];
    if (lane == 0) wsum[threadIdx.x >> 5] = make_float2(num, den);
    __syncthreads();
    if (threadIdx.x == 0) {
        float n = 0.f, d = 0.f;
#pragma unroll
        for (int i = 0; i < TPB / 32; i++) { n += wsum[i].x; d += wsum[i].y; }
        g_part[blockIdx.x] = make_float2(n, d);
    }
}

__global__ __launch_bounds__(256) void loss_reduce_kernel(float* __restrict__ out)
{
    __shared__ double sn[256];
    __shared__ double sd[256];
    double n = 0.0, d = 0.0;
    for (int i = threadIdx.x; i < NBLK; i += 256) {
        float2 v = g_part[i];
        n += (double)v.x;
        d += (double)v.y;
    }
    sn[threadIdx.x] = n;
    sd[threadIdx.x] = d;
    __syncthreads();
#pragma unroll
    for (int s = 128; s > 0; s >>= 1) {
        if (threadIdx.x < s) {
            sn[threadIdx.x] += sn[threadIdx.x + s];
            sd[threadIdx.x] += sd[threadIdx.x + s];
        }
        __syncthreads();
    }
    if (threadIdx.x == 0) out[0] = (float)(sn[0] / sd[0]);
}

extern "C" void kernel_launch(void* const* d_in, const int* in_sizes, int n_in,
                              void* d_out, int out_size)
{
    const float* logits = (const float*)d_in[0];
    const int*   labels = (const int*)d_in[1];
    const float* amask  = (const float*)d_in[2];
    float* out = (float*)d_out;

    loss_main_kernel<<<NBLK, TPB>>>(logits, labels, amask);
    loss_reduce_kernel<<<1, 256>>>(out);
}